// round 9
// baseline (speedup 1.0000x reference)
#include <cuda_runtime.h>
#include <math.h>

#define B_   16
#define T_   512
#define F_   17
#define K_   20
#define FEAT (F_*K_)        // 340
#define FL   30
#define NFR  (T_ - FL + 1)  // 483
#define TB   30             // 30*17 = 510 positions
#define NTBLK ((T_ + TB - 1) / TB)   // 18
#define EPSF 1e-12f

// Scratch: ping-pong activation buffers for both towers stacked as 32 "batches".
__device__ float g_bufA[2 * B_ * T_ * F_ * K_];
__device__ float g_bufB[2 * B_ * T_ * F_ * K_];

// Weights/biases in constant memory (warp-uniform -> LDC port, no L1TEX).
__constant__ __align__(16) float CW0[9 * 1  * K_];
__constant__ __align__(16) float CW1[9 * K_ * K_];
__constant__ __align__(16) float CW2[9 * K_ * K_];
__constant__ float CB0[K_];
__constant__ float CB1[K_];
__constant__ float CB2[K_];

// ---------------------------------------------------------------------------
// Layer 0 conv (CIN=1): tiny; 256 threads, 2 positions/thread.
// ---------------------------------------------------------------------------
__global__ void __launch_bounds__(256) conv1_kernel(
    const float* __restrict__ in0, const float* __restrict__ in1)
{
    extern __shared__ float tile[];   // (TB+2) * (F_+2)

    const int tid = threadIdx.x;
    const int t0  = blockIdx.x * TB;
    const int bb  = blockIdx.y;

    const float* src = (bb < B_) ? (in0 + (size_t)bb * T_ * F_)
                                 : (in1 + (size_t)(bb - B_) * T_ * F_);
    float* dst = g_bufA;

    const int tileN = (TB + 2) * (F_ + 2);
    for (int i = tid; i < tileN; i += 256) {
        int ff = i % (F_ + 2);
        int tt = i / (F_ + 2);
        int t = t0 - 1 + tt;
        int f = ff - 1;
        float v = 0.f;
        if (t >= 0 && t < T_ && f >= 0 && f < F_)
            v = src[(size_t)t * F_ + f];
        tile[i] = v;
    }
    __syncthreads();

    float acc0[K_], acc1[K_];
#pragma unroll
    for (int k = 0; k < K_; k++) { acc0[k] = CB0[k]; acc1[k] = CB0[k]; }

    const bool ok1 = (tid + 256 < TB * F_);
    const int pos0 = tid;
    const int pos1 = ok1 ? (tid + 256) : 0;
    const int lt0 = pos0 / F_, lf0 = pos0 % F_;
    const int lt1 = pos1 / F_, lf1 = pos1 % F_;

#pragma unroll
    for (int dt = 0; dt < 3; dt++) {
#pragma unroll
        for (int df = 0; df < 3; df++) {
            const int wbase = (dt * 3 + df) * K_;
            float i0 = tile[(lt0 + dt) * (F_ + 2) + lf0 + df];
            float i1 = tile[(lt1 + dt) * (F_ + 2) + lf1 + df];
#pragma unroll
            for (int k = 0; k < K_; k++) {
                float wv = CW0[wbase + k];
                acc0[k] = fmaf(i0, wv, acc0[k]);
                acc1[k] = fmaf(i1, wv, acc1[k]);
            }
        }
    }

    if ((t0 + lt0) < T_) {
        float* o = dst + (((size_t)bb * T_ + t0 + lt0) * F_ + lf0) * K_;
#pragma unroll
        for (int k = 0; k < K_; k++) o[k] = fmaxf(acc0[k], 0.f);
    }
    if (ok1 && (t0 + lt1) < T_) {
        float* o = dst + (((size_t)bb * T_ + t0 + lt1) * F_ + lf1) * K_;
#pragma unroll
        for (int k = 0; k < K_; k++) o[k] = fmaxf(acc1[k], 0.f);
    }
}

// ---------------------------------------------------------------------------
// Layers 1/2 conv (CIN=20): 128 threads, P=4 positions x 20 channels each.
// Per (cin,dt,df) step: 80 FFMA vs 5 LDC.128 + 4 LDS + ~8 overhead
// -> FFMA is ~82% of issue slots (was 61% at P=2).
// ---------------------------------------------------------------------------
#define CP 4
template<int SRC, int DST, int LAYER>
__global__ void __launch_bounds__(128) conv20_kernel()
{
    constexpr int CIN  = K_;
    constexpr int CINP = K_ + 1;    // 21: conflict-free lane stride

    extern __shared__ float tile[];   // (TB+2)*(F_+2)*CINP

    const int tid = threadIdx.x;
    const int t0  = blockIdx.x * TB;
    const int bb  = blockIdx.y;

    const float* src = ((SRC == 0) ? g_bufA : g_bufB) + (size_t)bb * T_ * F_ * CIN;
    float* dst = ((DST == 0) ? g_bufA : g_bufB);

    const int tileN = (TB + 2) * (F_ + 2) * CIN;
    for (int i = tid; i < tileN; i += 128) {
        int cin  = i % CIN;
        int rest = i / CIN;
        int ff   = rest % (F_ + 2);
        int tt   = rest / (F_ + 2);
        int t = t0 - 1 + tt;
        int f = ff - 1;
        float v = 0.f;
        if (t >= 0 && t < T_ && f >= 0 && f < F_)
            v = src[((size_t)t * F_ + f) * CIN + cin];
        tile[(tt * (F_ + 2) + ff) * CINP + cin] = v;
    }
    __syncthreads();

    float acc[CP * K_];
#pragma unroll
    for (int p = 0; p < CP; p++)
#pragma unroll
        for (int k = 0; k < K_; k++) {
            float bk = (LAYER == 1) ? CB1[k] : CB2[k];
            acc[p * K_ + k] = bk;
        }

    bool ok[CP];
    int  base[CP], ltv[CP], lfv[CP];
#pragma unroll
    for (int p = 0; p < CP; p++) {
        int pos = tid + p * 128;
        ok[p] = (pos < TB * F_);
        if (!ok[p]) pos = 0;
        ltv[p] = pos / F_;
        lfv[p] = pos % F_;
        base[p] = (ltv[p] * (F_ + 2) + lfv[p]) * CINP;
    }

    for (int cin = 0; cin < CIN; cin++) {
#pragma unroll
        for (int dt = 0; dt < 3; dt++) {
#pragma unroll
            for (int df = 0; df < 3; df++) {
                const int wbase = ((dt * 3 + df) * CIN + cin) * K_;  // 80B-aligned
                const int off = (dt * (F_ + 2) + df) * CINP + cin;   // base + const
                float in[CP];
#pragma unroll
                for (int p = 0; p < CP; p++) in[p] = tile[base[p] + off];
#pragma unroll
                for (int q = 0; q < 5; q++) {
                    float4 wv = (LAYER == 1)
                        ? reinterpret_cast<const float4*>(CW1 + wbase)[q]
                        : reinterpret_cast<const float4*>(CW2 + wbase)[q];
#pragma unroll
                    for (int p = 0; p < CP; p++) {
                        acc[p * K_ + 4*q+0] = fmaf(in[p], wv.x, acc[p * K_ + 4*q+0]);
                        acc[p * K_ + 4*q+1] = fmaf(in[p], wv.y, acc[p * K_ + 4*q+1]);
                        acc[p * K_ + 4*q+2] = fmaf(in[p], wv.z, acc[p * K_ + 4*q+2]);
                        acc[p * K_ + 4*q+3] = fmaf(in[p], wv.w, acc[p * K_ + 4*q+3]);
                    }
                }
            }
        }
    }

#pragma unroll
    for (int p = 0; p < CP; p++) {
        int t = t0 + ltv[p];
        if (ok[p] && t < T_) {
            float* o = dst + (((size_t)bb * T_ + t) * F_ + lfv[p]) * K_;
#pragma unroll
            for (int k = 0; k < K_; k++) o[k] = fmaxf(acc[p * K_ + k], 0.f);
        }
    }
}

// ---------------------------------------------------------------------------
// Per-frame double-normalized cross-correlation. Final conv output in g_bufA.
// Phase A: each thread owns column-tasks (680 total); loads the 30 column
//   values from GLOBAL into registers (coalesced), computes mu/sigma, writes
//   NORMALIZED values to smem. Both towers staged-normalized: one global pass,
//   minimal smem passes.
// Phase B: row reductions, pure LDS: 2 loads + 5 FMA per element; second
//   normalization handled algebraically from 5 warp-reduced sums.
// ---------------------------------------------------------------------------
__global__ void __launch_bounds__(256) corr_kernel(float* __restrict__ out)
{
    extern __shared__ float sm[];          // 2 * FL * FEAT floats (81600 B)
    float* sS = sm;
    float* sX = sm + FL * FEAT;
    __shared__ float red[8];

    const int fr  = blockIdx.x;   // 0..482
    const int b   = blockIdx.y;   // 0..15
    const int tid = threadIdx.x;

    const float* S = g_bufA + ((size_t)b * T_ + fr) * FEAT;
    const float* X = g_bufA + ((size_t)(b + B_) * T_ + fr) * FEAT;

    // Phase A: column normalize via register staging (680 tasks).
    for (int task = tid; task < 2 * FEAT; task += 256) {
        const bool isS = (task < FEAT);
        const int col = isS ? task : task - FEAT;
        const float* src = isS ? S : X;
        float* dsm = isS ? sS : sX;

        float v[FL];
        float s = 0.f, s2 = 0.f;
#pragma unroll
        for (int t = 0; t < FL; t++) {
            v[t] = src[t * FEAT + col];    // coalesced across lanes
            s += v[t]; s2 += v[t] * v[t];
        }
        float mu  = s * (1.0f / FL);
        float var = fmaxf(s2 - (float)FL * mu * mu, 0.f);
        float inv = 1.f / (sqrtf(var) + EPSF);
#pragma unroll
        for (int t = 0; t < FL; t++)
            dsm[t * FEAT + col] = (v[t] - mu) * inv;
    }
    __syncthreads();

    // Phase B: one warp per row, 8 warps round-robin over 30 rows.
    const int warp = tid >> 5, lane = tid & 31;
    float acc = 0.f;
    for (int t = warp; t < FL; t += 8) {
        float aU = 0.f, aV = 0.f, a2U = 0.f, a2V = 0.f, aUV = 0.f;
        for (int c = lane; c < FEAT; c += 32) {
            float u = sS[t * FEAT + c];
            float v = sX[t * FEAT + c];
            aU += u; aV += v; a2U += u * u; a2V += v * v; aUV += u * v;
        }
#pragma unroll
        for (int o = 16; o > 0; o >>= 1) {
            aU  += __shfl_down_sync(0xffffffffu, aU,  o);
            aV  += __shfl_down_sync(0xffffffffu, aV,  o);
            a2U += __shfl_down_sync(0xffffffffu, a2U, o);
            a2V += __shfl_down_sync(0xffffffffu, a2V, o);
            aUV += __shfl_down_sync(0xffffffffu, aUV, o);
        }
        if (lane == 0) {
            float muU = aU * (1.0f / FEAT), muV = aV * (1.0f / FEAT);
            float sgU = sqrtf(fmaxf(a2U - (float)FEAT * muU * muU, 0.f));
            float sgV = sqrtf(fmaxf(a2V - (float)FEAT * muV * muV, 0.f));
            float dot = aUV - (float)FEAT * muU * muV;
            acc += dot / ((sgU + EPSF) * (sgV + EPSF));
        }
    }
    if (lane == 0) red[warp] = acc;
    __syncthreads();
    if (tid == 0) {
        float tot = 0.f;
#pragma unroll
        for (int i = 0; i < 8; i++) tot += red[i];
        atomicAdd(&out[b], tot * (1.0f / ((float)FL * (float)NFR)));
    }
}

__global__ void zero_out(float* out, int n)
{
    int i = blockIdx.x * blockDim.x + threadIdx.x;
    if (i < n) out[i] = 0.f;
}

extern "C" void kernel_launch(void* const* d_in, const int* in_sizes, int n_in,
                              void* d_out, int out_size)
{
    const float* s  = (const float*)d_in[0];
    const float* x  = (const float*)d_in[1];
    const float* w0 = (const float*)d_in[2];
    const float* b0 = (const float*)d_in[3];
    const float* w1 = (const float*)d_in[4];
    const float* b1 = (const float*)d_in[5];
    const float* w2 = (const float*)d_in[6];
    const float* b2 = (const float*)d_in[7];
    float* out = (float*)d_out;

    // D2D copies into constant memory (graph-capturable memcpy nodes).
    cudaMemcpyToSymbolAsync(CW0, w0, 9 * 1  * K_ * sizeof(float), 0, cudaMemcpyDeviceToDevice, 0);
    cudaMemcpyToSymbolAsync(CB0, b0, K_ * sizeof(float),          0, cudaMemcpyDeviceToDevice, 0);
    cudaMemcpyToSymbolAsync(CW1, w1, 9 * K_ * K_ * sizeof(float), 0, cudaMemcpyDeviceToDevice, 0);
    cudaMemcpyToSymbolAsync(CB1, b1, K_ * sizeof(float),          0, cudaMemcpyDeviceToDevice, 0);
    cudaMemcpyToSymbolAsync(CW2, w2, 9 * K_ * K_ * sizeof(float), 0, cudaMemcpyDeviceToDevice, 0);
    cudaMemcpyToSymbolAsync(CB2, b2, K_ * sizeof(float),          0, cudaMemcpyDeviceToDevice, 0);

    zero_out<<<1, 32>>>(out, out_size);

    const int smem1  = (TB + 2) * (F_ + 2) * (int)sizeof(float);            //  2432 B
    const int smem20 = (TB + 2) * (F_ + 2) * 21 * (int)sizeof(float);       // 51072 B
    const int smemC  = 2 * FL * FEAT * (int)sizeof(float);                  // 81600 B

    cudaFuncSetAttribute(conv20_kernel<0, 1, 1>,
                         cudaFuncAttributeMaxDynamicSharedMemorySize, smem20);
    cudaFuncSetAttribute(conv20_kernel<1, 0, 2>,
                         cudaFuncAttributeMaxDynamicSharedMemorySize, smem20);
    cudaFuncSetAttribute(corr_kernel,
                         cudaFuncAttributeMaxDynamicSharedMemorySize, smemC);

    dim3 cgrid(NTBLK, 2 * B_);   // 18 x 32 = 576 CTAs
    conv1_kernel<<<cgrid, 256, smem1>>>(s, x);         // -> bufA
    conv20_kernel<0, 1, 1><<<cgrid, 128, smem20>>>();  // A -> B
    conv20_kernel<1, 0, 2><<<cgrid, 128, smem20>>>();  // B -> A

    dim3 ggrid(NFR, B_);
    corr_kernel<<<ggrid, 256, smemC>>>(out);
}

// round 11
// speedup vs baseline: 1.1317x; 1.1317x over previous
#include <cuda_runtime.h>
#include <cuda_bf16.h>
#include <math.h>

#define B_   16
#define T_   512
#define F_   17
#define K_   20
#define FEAT (F_*K_)        // 340
#define FL   30
#define NFR  (T_ - FL + 1)  // 483
#define TB   30             // 30*17 = 510 positions ~= 2*256 thread-slots
#define NTBLK ((T_ + TB - 1) / TB)   // 18
#define EPSF 1e-12f

// Scratch: ping-pong activation buffers for both towers stacked as 32 "batches".
__device__ float g_bufA[2 * B_ * T_ * F_ * K_];
__device__ float g_bufB[2 * B_ * T_ * F_ * K_];

// Weights/biases in constant memory (warp-uniform -> LDC port, no L1TEX).
__constant__ __align__(16) float CW0[9 * 1  * K_];
__constant__ __align__(16) float CW1[9 * K_ * K_];
__constant__ __align__(16) float CW2[9 * K_ * K_];
__constant__ float CB0[K_];
__constant__ float CB1[K_];
__constant__ float CB2[K_];

// ---------------------------------------------------------------------------
// Conv 3x3 SAME + bias + ReLU — EXACT round-7 winner (80.7us per CIN=20 layer).
// 256 threads, 2 positions/thread, TB=30 (510/512 slots useful),
// grid 18x32 = 576 CTAs = one full wave at 4 CTAs/SM (32 warps/SM).
// ---------------------------------------------------------------------------
template<int CIN, bool FIRST, int SRC, int DST, int LAYER>
__global__ void __launch_bounds__(256) conv_kernel(
    const float* __restrict__ in0, const float* __restrict__ in1)
{
    constexpr int CINP = (CIN % 2 == 0) ? CIN + 1 : CIN;   // 21 for 20, 1 for 1

    extern __shared__ float tile[];   // (TB+2) * (F_+2) * CINP floats

    const int tid = threadIdx.x;
    const int t0  = blockIdx.x * TB;
    const int bb  = blockIdx.y;   // 0..31 (0..15 = S tower, 16..31 = X tower)

    const float* src;
    if (FIRST) {
        src = (bb < B_) ? (in0 + (size_t)bb * T_ * F_)
                        : (in1 + (size_t)(bb - B_) * T_ * F_);
    } else {
        const float* base = (SRC == 0) ? g_bufA : g_bufB;
        src = base + (size_t)bb * T_ * F_ * CIN;
    }
    float* dst = ((DST == 0) ? g_bufA : g_bufB);

    const int tileN = (TB + 2) * (F_ + 2) * CIN;
    for (int i = tid; i < tileN; i += 256) {
        int cin  = i % CIN;
        int rest = i / CIN;
        int ff   = rest % (F_ + 2);
        int tt   = rest / (F_ + 2);
        int t = t0 - 1 + tt;
        int f = ff - 1;
        float v = 0.f;
        if (t >= 0 && t < T_ && f >= 0 && f < F_)
            v = src[((size_t)t * F_ + f) * CIN + cin];
        tile[(tt * (F_ + 2) + ff) * CINP + cin] = v;
    }
    __syncthreads();

    float acc0[K_], acc1[K_];
#pragma unroll
    for (int k = 0; k < K_; k++) {
        float bk;
        if constexpr (LAYER == 0) bk = CB0[k];
        else if constexpr (LAYER == 1) bk = CB1[k];
        else bk = CB2[k];
        acc0[k] = bk; acc1[k] = bk;
    }

    const bool ok0 = (tid < TB * F_);
    const bool ok1 = (tid + 256 < TB * F_);
    const int pos0 = ok0 ? tid : 0;
    const int pos1 = ok1 ? (tid + 256) : 0;
    const int lt0 = pos0 / F_, lf0 = pos0 % F_;
    const int lt1 = pos1 / F_, lf1 = pos1 % F_;

    for (int cin = 0; cin < CIN; cin++) {
#pragma unroll
        for (int dt = 0; dt < 3; dt++) {
#pragma unroll
            for (int df = 0; df < 3; df++) {
                const int wbase = ((dt * 3 + df) * CIN + cin) * K_;  // 80B-aligned
                float i0 = tile[((lt0 + dt) * (F_ + 2) + lf0 + df) * CINP + cin];
                float i1 = tile[((lt1 + dt) * (F_ + 2) + lf1 + df) * CINP + cin];
#pragma unroll
                for (int q = 0; q < 5; q++) {
                    float4 wv;
                    if constexpr (LAYER == 0)
                        wv = reinterpret_cast<const float4*>(CW0 + wbase)[q];
                    else if constexpr (LAYER == 1)
                        wv = reinterpret_cast<const float4*>(CW1 + wbase)[q];
                    else
                        wv = reinterpret_cast<const float4*>(CW2 + wbase)[q];
                    acc0[4*q+0] = fmaf(i0, wv.x, acc0[4*q+0]);
                    acc0[4*q+1] = fmaf(i0, wv.y, acc0[4*q+1]);
                    acc0[4*q+2] = fmaf(i0, wv.z, acc0[4*q+2]);
                    acc0[4*q+3] = fmaf(i0, wv.w, acc0[4*q+3]);
                    acc1[4*q+0] = fmaf(i1, wv.x, acc1[4*q+0]);
                    acc1[4*q+1] = fmaf(i1, wv.y, acc1[4*q+1]);
                    acc1[4*q+2] = fmaf(i1, wv.z, acc1[4*q+2]);
                    acc1[4*q+3] = fmaf(i1, wv.w, acc1[4*q+3]);
                }
            }
        }
    }

    if (ok0 && (t0 + lt0) < T_) {
        int t = t0 + lt0;
        float* o = dst + (((size_t)bb * T_ + t) * F_ + lf0) * K_;
#pragma unroll
        for (int k = 0; k < K_; k++) o[k] = fmaxf(acc0[k], 0.f);
    }
    if (ok1 && (t0 + lt1) < T_) {
        int t = t0 + lt1;
        float* o = dst + (((size_t)bb * T_ + t) * F_ + lf1) * K_;
#pragma unroll
        for (int k = 0; k < K_; k++) o[k] = fmaxf(acc1[k], 0.f);
    }
}

// ---------------------------------------------------------------------------
// Per-frame double-normalized cross-correlation. Final conv output in g_bufA.
// Phase A: register-staged column normalize (one coalesced global pass);
//   normalized values stored to smem as BF16 (z is O(1), rounding averages
//   out over 340*30*483 reductions).
// Phase B: row reductions reading bf16x2 pairs (half the LDS wavefronts).
// smem = 2 * 30*340 * 2B = 40.8KB static -> 5 CTAs/SM (was 2 at fp32).
// ---------------------------------------------------------------------------
__global__ void __launch_bounds__(256) corr_kernel(float* __restrict__ out)
{
    __shared__ __nv_bfloat16 sS[FL * FEAT];   // 20400 B
    __shared__ __nv_bfloat16 sX[FL * FEAT];   // 20400 B
    __shared__ float red[8];

    const int fr  = blockIdx.x;   // 0..482
    const int b   = blockIdx.y;   // 0..15
    const int tid = threadIdx.x;

    const float* S = g_bufA + ((size_t)b * T_ + fr) * FEAT;
    const float* X = g_bufA + ((size_t)(b + B_) * T_ + fr) * FEAT;

    // Phase A: 680 column tasks; load 30 values into registers (coalesced),
    // normalize, store bf16 to smem.
    for (int task = tid; task < 2 * FEAT; task += 256) {
        const bool isS = (task < FEAT);
        const int col = isS ? task : task - FEAT;
        const float* src = isS ? S : X;
        __nv_bfloat16* dsm = isS ? sS : sX;

        float v[FL];
        float s = 0.f, s2 = 0.f;
#pragma unroll
        for (int t = 0; t < FL; t++) {
            v[t] = src[t * FEAT + col];
            s += v[t]; s2 += v[t] * v[t];
        }
        float mu  = s * (1.0f / FL);
        float var = fmaxf(s2 - (float)FL * mu * mu, 0.f);
        float inv = 1.f / (sqrtf(var) + EPSF);
#pragma unroll
        for (int t = 0; t < FL; t++)
            dsm[t * FEAT + col] = __float2bfloat16((v[t] - mu) * inv);
    }
    __syncthreads();

    // Phase B: one warp per row, 8 warps over 30 rows; bf16x2 loads.
    const int warp = tid >> 5, lane = tid & 31;
    float acc = 0.f;
    for (int t = warp; t < FL; t += 8) {
        const __nv_bfloat162* rS = reinterpret_cast<const __nv_bfloat162*>(sS + t * FEAT);
        const __nv_bfloat162* rX = reinterpret_cast<const __nv_bfloat162*>(sX + t * FEAT);
        float aU = 0.f, aV = 0.f, a2U = 0.f, a2V = 0.f, aUV = 0.f;
        // FEAT=340 -> 170 bf16x2 pairs; warp strides 32 pairs: 5 full + 10-lane tail.
#pragma unroll
        for (int j = 0; j < 6; j++) {
            int pi = j * 32 + lane;
            if (pi < FEAT / 2) {
                float2 u2 = __bfloat1622float2(rS[pi]);
                float2 v2 = __bfloat1622float2(rX[pi]);
                aU += u2.x + u2.y;
                aV += v2.x + v2.y;
                a2U = fmaf(u2.x, u2.x, fmaf(u2.y, u2.y, a2U));
                a2V = fmaf(v2.x, v2.x, fmaf(v2.y, v2.y, a2V));
                aUV = fmaf(u2.x, v2.x, fmaf(u2.y, v2.y, aUV));
            }
        }
#pragma unroll
        for (int o = 16; o > 0; o >>= 1) {
            aU  += __shfl_down_sync(0xffffffffu, aU,  o);
            aV  += __shfl_down_sync(0xffffffffu, aV,  o);
            a2U += __shfl_down_sync(0xffffffffu, a2U, o);
            a2V += __shfl_down_sync(0xffffffffu, a2V, o);
            aUV += __shfl_down_sync(0xffffffffu, aUV, o);
        }
        if (lane == 0) {
            float muU = aU * (1.0f / FEAT), muV = aV * (1.0f / FEAT);
            float sgU = sqrtf(fmaxf(a2U - (float)FEAT * muU * muU, 0.f));
            float sgV = sqrtf(fmaxf(a2V - (float)FEAT * muV * muV, 0.f));
            float dot = aUV - (float)FEAT * muU * muV;
            acc += dot / ((sgU + EPSF) * (sgV + EPSF));
        }
    }
    if (lane == 0) red[warp] = acc;
    __syncthreads();
    if (tid == 0) {
        float tot = 0.f;
#pragma unroll
        for (int i = 0; i < 8; i++) tot += red[i];
        atomicAdd(&out[b], tot * (1.0f / ((float)FL * (float)NFR)));
    }
}

__global__ void zero_out(float* out, int n)
{
    int i = blockIdx.x * blockDim.x + threadIdx.x;
    if (i < n) out[i] = 0.f;
}

extern "C" void kernel_launch(void* const* d_in, const int* in_sizes, int n_in,
                              void* d_out, int out_size)
{
    const float* s  = (const float*)d_in[0];
    const float* x  = (const float*)d_in[1];
    const float* w0 = (const float*)d_in[2];
    const float* b0 = (const float*)d_in[3];
    const float* w1 = (const float*)d_in[4];
    const float* b1 = (const float*)d_in[5];
    const float* w2 = (const float*)d_in[6];
    const float* b2 = (const float*)d_in[7];
    float* out = (float*)d_out;

    // D2D copies into constant memory (graph-capturable memcpy nodes).
    cudaMemcpyToSymbolAsync(CW0, w0, 9 * 1  * K_ * sizeof(float), 0, cudaMemcpyDeviceToDevice, 0);
    cudaMemcpyToSymbolAsync(CB0, b0, K_ * sizeof(float),          0, cudaMemcpyDeviceToDevice, 0);
    cudaMemcpyToSymbolAsync(CW1, w1, 9 * K_ * K_ * sizeof(float), 0, cudaMemcpyDeviceToDevice, 0);
    cudaMemcpyToSymbolAsync(CB1, b1, K_ * sizeof(float),          0, cudaMemcpyDeviceToDevice, 0);
    cudaMemcpyToSymbolAsync(CW2, w2, 9 * K_ * K_ * sizeof(float), 0, cudaMemcpyDeviceToDevice, 0);
    cudaMemcpyToSymbolAsync(CB2, b2, K_ * sizeof(float),          0, cudaMemcpyDeviceToDevice, 0);

    zero_out<<<1, 32>>>(out, out_size);

    const int smem1  = (TB + 2) * (F_ + 2) * 1  * (int)sizeof(float);  //  2432 B
    const int smem20 = (TB + 2) * (F_ + 2) * 21 * (int)sizeof(float);  // 51072 B

    cudaFuncSetAttribute(conv_kernel<K_, false, 0, 1, 1>,
                         cudaFuncAttributeMaxDynamicSharedMemorySize, smem20);
    cudaFuncSetAttribute(conv_kernel<K_, false, 1, 0, 2>,
                         cudaFuncAttributeMaxDynamicSharedMemorySize, smem20);

    dim3 cgrid(NTBLK, 2 * B_);   // 18 x 32 = 576 CTAs
    conv_kernel<1,  true,  0, 0, 0><<<cgrid, 256, smem1 >>>(s, x);             // -> bufA
    conv_kernel<K_, false, 0, 1, 1><<<cgrid, 256, smem20>>>(nullptr, nullptr); // A -> B
    conv_kernel<K_, false, 1, 0, 2><<<cgrid, 256, smem20>>>(nullptr, nullptr); // B -> A

    dim3 ggrid(NFR, B_);
    corr_kernel<<<ggrid, 256>>>(out);
}